// round 3
// baseline (speedup 1.0000x reference)
#include <cuda_runtime.h>

// LSTM: B=128, T=2048, F=3, U=256. Persistent kernel, 128 CTAs = 16 batch-groups x 8 gate-column blocks.
// R2: packed fma.rn.f32x2 GEMM (FFMA2, bit-exact fp32, 2 MACs/lane/instr), duplicated-h SMEM layout
//     (stride 516 -> conflict-free LDS.64 pairs), L2 h-load latency hidden under acc-init,
//     direct scattered STG epilogue (no hns staging), all-thread acquire-spin barrier.

#define BB 128
#define TT 2048
#define FF 3
#define UU 256
#define G4 1024
#define NCTA 128
#define NTHR 256

__device__ float    g_h[2][BB * UU];     // ping-pong hidden state
__device__ unsigned g_bar[16 * 32];      // one counter per group, 128B apart

// SMEM layout (float offsets)
#define OFF_WH   0        // 256*128 = 32768  (permuted Wh slice: [k][unit_local*4+gate])
#define OFF_HS   32768    // 8*516   = 4128   (h tile DUPLICATED: [b][2k]=[b][2k+1]=h_k, stride 516)
#define OFF_BIAS 36896    // 128              (permuted bias slice)
#define OFF_WX   37024    // 384              (permuted Wx slice)
#define OFF_XS   37408    // 32               (x[t] tile)
#define SMEM_FLOATS 37440
#define SMEM_BYTES (SMEM_FLOATS * 4)
#define HSTRIDE 516

__device__ __forceinline__ float sig_f(float x) {
    x = fminf(fmaxf(x, -30.f), 30.f);
    float e = __expf(-x);
    return __fdividef(1.f, 1.f + e);
}

__device__ __forceinline__ float tanh_f(float x) {
    float ax = fminf(fabsf(x), 15.f);
    float e = __expf(-2.f * ax);
    float r = __fdividef(1.f - e, 1.f + e);
    return copysignf(r, x);
}

__device__ __forceinline__ void ffma2(unsigned long long& acc,
                                      unsigned long long a,
                                      unsigned long long b) {
    asm("fma.rn.f32x2 %0, %1, %2, %0;" : "+l"(acc) : "l"(a), "l"(b));
}

__device__ __forceinline__ unsigned ld_acq(const unsigned* p) {
    unsigned v;
    asm volatile("ld.global.acquire.gpu.u32 %0, [%1];" : "=r"(v) : "l"(p));
    return v;
}

__global__ void lstm_init_kernel() {
    int i = blockIdx.x * blockDim.x + threadIdx.x;
    if (i < 2 * BB * UU) ((float*)g_h)[i] = 0.f;
    if (i < 16 * 32) g_bar[i] = 0u;
}

__global__ void __launch_bounds__(NTHR, 1) lstm_persistent_kernel(
    const float* __restrict__ x,     // [B, T, F]
    const float* __restrict__ Wx,    // [F, 4U]
    const float* __restrict__ Wh,    // [U, 4U]
    const float* __restrict__ bias,  // [4U]
    float* __restrict__ out,         // ys [B,T,U] (+ h_T, c_T if write_hc)
    int write_hc)
{
    extern __shared__ float sm[];
    float* whs = sm + OFF_WH;
    float* hs2 = sm + OFF_HS;
    float* bs  = sm + OFF_BIAS;
    float* wxs = sm + OFF_WX;
    float* xs  = sm + OFF_XS;

    const int tid = threadIdx.x;
    const int RB  = blockIdx.x >> 3;   // batch-group 0..15
    const int CB  = blockIdx.x & 7;    // gate-column block 0..7
    const int gb  = RB * 8;

    // ---------------- setup: permuted weights -> SMEM ----------------
    #pragma unroll
    for (int g = 0; g < 4; g++) {
        const int gbase = g * UU + CB * 32;
        for (int i = tid; i < 256 * 32; i += NTHR) {
            int k = i >> 5, ul = i & 31;
            whs[k * 128 + ul * 4 + g] = Wh[k * G4 + gbase + ul];
        }
        for (int i = tid; i < 3 * 32; i += NTHR) {
            int f = i >> 5, ul = i & 31;
            wxs[f * 128 + ul * 4 + g] = Wx[f * G4 + gbase + ul];
        }
    }
    if (tid < 128) {
        int ul = tid >> 2, g = tid & 3;
        bs[tid] = bias[g * UU + CB * 32 + ul];
    }

    const int u_l = tid >> 3;   // 0..31
    const int b_l = tid & 7;    // 0..7
    const int gcol = CB * 32 + u_l;

    float c = 0.f;

    float xpre = 0.f;
    if (tid < 24) xpre = __ldg(&x[(size_t)(gb + tid / 3) * (TT * FF) + tid % 3]);

    unsigned* barp = &g_bar[RB * 32];

    __syncthreads();

    for (int s = 0; s < TT; s++) {
        // -------- issue h loads early (MLP=4), hide L2 latency under init --------
        float2 hv4[4];
        {
            const float2* hg = reinterpret_cast<const float2*>(g_h[s & 1] + (size_t)gb * UU);
            #pragma unroll
            for (int it = 0; it < 4; it++)
                hv4[it] = __ldcg(&hg[tid + it * 256]);
        }
        if (tid < 24) xs[tid] = xpre;
        __syncthreads();   // xs visible

        // -------- acc init: bias + x @ Wx (overlaps h-load flight) --------
        float a0, a1, a2, a3;
        {
            float4 bb4 = *reinterpret_cast<const float4*>(bs + u_l * 4);
            a0 = bb4.x; a1 = bb4.y; a2 = bb4.z; a3 = bb4.w;
            float xv0 = xs[b_l * 3 + 0], xv1 = xs[b_l * 3 + 1], xv2 = xs[b_l * 3 + 2];
            float4 w;
            w = *reinterpret_cast<const float4*>(wxs + 0 * 128 + u_l * 4);
            a0 = fmaf(xv0, w.x, a0); a1 = fmaf(xv0, w.y, a1);
            a2 = fmaf(xv0, w.z, a2); a3 = fmaf(xv0, w.w, a3);
            w = *reinterpret_cast<const float4*>(wxs + 1 * 128 + u_l * 4);
            a0 = fmaf(xv1, w.x, a0); a1 = fmaf(xv1, w.y, a1);
            a2 = fmaf(xv1, w.z, a2); a3 = fmaf(xv1, w.w, a3);
            w = *reinterpret_cast<const float4*>(wxs + 2 * 128 + u_l * 4);
            a0 = fmaf(xv2, w.x, a0); a1 = fmaf(xv2, w.y, a1);
            a2 = fmaf(xv2, w.z, a2); a3 = fmaf(xv2, w.w, a3);
        }

        // prefetch next x
        if (tid < 24 && s + 1 < TT)
            xpre = __ldg(&x[(size_t)(gb + tid / 3) * (TT * FF) + (size_t)(s + 1) * FF + tid % 3]);

        // -------- stage h duplicated: hs2[b][2k]=hs2[b][2k+1]=h_k --------
        #pragma unroll
        for (int it = 0; it < 4; it++) {
            int i = tid + it * 256;       // pair index over 8*128
            int b = i >> 7, kp = i & 127;
            *reinterpret_cast<float4*>(hs2 + b * HSTRIDE + kp * 4) =
                make_float4(hv4[it].x, hv4[it].x, hv4[it].y, hv4[it].y);
        }
        __syncthreads();

        // -------- GEMM: z += h @ Wh, packed f32x2 (K=256) --------
        unsigned long long a01, a23;
        asm("mov.b64 %0, {%1, %2};" : "=l"(a01) : "f"(a0), "f"(a1));
        asm("mov.b64 %0, {%1, %2};" : "=l"(a23) : "f"(a2), "f"(a3));
        {
            const float* whp = whs + u_l * 4;
            const unsigned long long* hp =
                reinterpret_cast<const unsigned long long*>(hs2 + b_l * HSTRIDE);
            #pragma unroll 8
            for (int k = 0; k < UU; k++) {
                ulonglong2 wv = *reinterpret_cast<const ulonglong2*>(whp + k * 128);
                unsigned long long hv = hp[k];
                ffma2(a01, hv, wv.x);
                ffma2(a23, hv, wv.y);
            }
        }
        asm("mov.b64 {%0, %1}, %2;" : "=f"(a0), "=f"(a1) : "l"(a01));
        asm("mov.b64 {%0, %1}, %2;" : "=f"(a2), "=f"(a3) : "l"(a23));

        // -------- gates / state update / direct stores --------
        {
            float ig = sig_f(a0);
            float fg = sig_f(a1);
            float gg = tanh_f(a2);
            float og = sig_f(a3);
            c = fmaf(fg, c, ig * gg);
            float hn = og * tanh_f(c);
            __stcg(&g_h[(s + 1) & 1][(size_t)(gb + b_l) * UU + gcol], hn);
            out[(size_t)(gb + b_l) * (TT * UU) + (size_t)s * UU + gcol] = hn;
            if (s == TT - 1 && write_hc) {
                out[(size_t)BB * TT * UU + (size_t)(gb + b_l) * UU + gcol] = hn;
                out[(size_t)BB * TT * UU + (size_t)BB * UU + (size_t)(gb + b_l) * UU + gcol] = c;
            }
        }

        // -------- per-group barrier: release-add + all-thread acquire spin --------
        if (s + 1 < TT) {
            __syncthreads();                 // all STGs issued, CTA quiesced
            if (tid == 0) {
                __threadfence();             // release our h stores to gpu scope
                atomicAdd(barp, 1u);
            }
            unsigned tgt = 8u * (unsigned)(s + 1);
            while (ld_acq(barp) < tgt) { }   // acquire: peers' h visible after exit
        }
    }
}

extern "C" void kernel_launch(void* const* d_in, const int* in_sizes, int n_in,
                              void* d_out, int out_size) {
    const float* x    = (const float*)d_in[0];
    const float* Wx   = (const float*)d_in[1];
    const float* Wh   = (const float*)d_in[2];
    const float* bias = (const float*)d_in[3];
    float* out = (float*)d_out;

    long long need = (long long)BB * TT * UU + 2LL * BB * UU;
    int write_hc = ((long long)out_size >= need) ? 1 : 0;

    cudaFuncSetAttribute(lstm_persistent_kernel,
                         cudaFuncAttributeMaxDynamicSharedMemorySize, SMEM_BYTES);

    lstm_init_kernel<<<256, 256>>>();
    lstm_persistent_kernel<<<NCTA, NTHR, SMEM_BYTES>>>(x, Wx, Wh, bias, out, write_hc);
}